// round 13
// baseline (speedup 1.0000x reference)
#include <cuda_runtime.h>
#include <cuda_fp16.h>

// ---------------------------------------------------------------------------
// VQ-VAE vector quantizer: CHEAP fp16 HMMA rank (score = e2 - 2*z.e_h, K=128,
// A=[z_h|z_m], B=[e_h|e_h]) -> 32 slot-candidates -> approx top-8 ->
// exact-fp32 refine over 8 (bitwise round-2 comparator) decides.
//   z: [32, 64, 64, 64] fp32, emb_w: [1024, 64] fp32.
// R13: mainloop structure EXACTLY R10 (2Mx4N, 2 barriers, CP_WAIT1); only the
//      K-extent, candidate selection, and refine width change.
// ---------------------------------------------------------------------------

#define N_TOK    131072
#define K_CODES  1024
#define D_DIM    64
#define TOK_CTA  128
#define NCTA     (N_TOK / TOK_CTA)     // 1024
#define CHUNK    64                    // codes per chunk
#define NCHUNK   (K_CODES / CHUNK)     // 16
#define KTOT     128                   // 2 x 64 segments: z_h|z_m  vs  e_h|e_h
#define KP       136                   // padded smem stride (halves); 272B rows
#define THREADS  256
#define NCAND    8

#define A_SZ     (TOK_CTA * KP * 2)    // 34816 B
#define B_SZ     (CHUNK * KP * 2)      // 17408 B per buffer
#define SM_A     0
#define SM_B     A_SZ                  // two buffers (34816 B total)
#define SM_E2    (SM_A + A_SZ + 2 * B_SZ)   // 69632
#define SMEM_TOTAL (SM_E2 + K_CODES * 4)    // 73728

// candidate dump arrays reuse the B region after the mainloop: 4 x 8KB = 32KB
#define SV1_OFF  SM_B
#define SI1_OFF  (SM_B + 8192)
#define SV2_OFF  (SM_B + 16384)
#define SI2_OFF  (SM_B + 24576)

typedef unsigned int u32;

__device__ __align__(16) __half g_ef[K_CODES * KTOT];  // [code][e_h | e_h]
__device__ float  g_e2[K_CODES];
__device__ int    g_cand[N_TOK * NCAND];   // 8 candidates per token
__device__ int    g_idx[N_TOK];            // refined argmin
__device__ double g_loss;

// ---------------- PTX helpers ----------------------------------------------
__device__ __forceinline__ u32 smem_u32(const void* p) {
    u32 a;
    asm("{ .reg .u64 t; cvta.to.shared.u64 t, %1; cvt.u32.u64 %0, t; }" : "=r"(a) : "l"(p));
    return a;
}
#define LDSM4(r, addr)                                                                   \
    asm volatile("ldmatrix.sync.aligned.m8n8.x4.shared.b16 {%0,%1,%2,%3}, [%4];"         \
        : "=r"((r)[0]), "=r"((r)[1]), "=r"((r)[2]), "=r"((r)[3]) : "r"(addr))
#define MMA16816(d, a, b0, b1)                                                           \
    asm volatile("mma.sync.aligned.m16n8k16.row.col.f32.f16.f16.f32 "                    \
        "{%0,%1,%2,%3}, {%4,%5,%6,%7}, {%8,%9}, {%0,%1,%2,%3};"                          \
        : "+f"((d)[0]), "+f"((d)[1]), "+f"((d)[2]), "+f"((d)[3])                         \
        : "r"((a)[0]), "r"((a)[1]), "r"((a)[2]), "r"((a)[3]), "r"(b0), "r"(b1))
#define CP16(dst, src)                                                                   \
    asm volatile("cp.async.cg.shared.global [%0], [%1], 16;" :: "r"(dst), "l"(src))
#define CP_COMMIT() asm volatile("cp.async.commit_group;" ::: "memory")
#define CP_WAIT1()  asm volatile("cp.async.wait_group 1;" ::: "memory")
#define CP_WAIT0()  asm volatile("cp.async.wait_group 0;" ::: "memory")

// ---------------------------------------------------------------------------
// K0: codebook e_h (duplicated) + ||e||^2 + zero loss
// ---------------------------------------------------------------------------
__global__ void vq_prep(const float* __restrict__ emb) {
    int t = blockIdx.x * blockDim.x + threadIdx.x;   // 8192 threads
    if (t == 0) g_loss = 0.0;
    for (int i = t; i < K_CODES * D_DIM; i += 8192) {
        int c = i >> 6, k = i & 63;
        __half h = __float2half_rn(emb[i]);
        g_ef[c * KTOT + k]      = h;   // pairs with z_h
        g_ef[c * KTOT + 64 + k] = h;   // pairs with z_m  -> together: z . e_h
    }
    if (t < K_CODES) {
        const float4* row = (const float4*)(emb + t * D_DIM);
        float s = 0.f;
#pragma unroll
        for (int i = 0; i < 16; i++) {
            float4 v = row[i];
            s += v.x * v.x + v.y * v.y + v.z * v.z + v.w * v.w;
        }
        g_e2[t] = s;
    }
}

// ---------------------------------------------------------------------------
// K1: HMMA candidate ranking + top-8 select. 1024 CTAs x 128 tokens.
// 8 warps (2M x 4N), warp tile 64x16, chunk = 64 codes double-buffered.
// ---------------------------------------------------------------------------
__device__ __forceinline__ void issue_B(u32 sb, int buf, int chunk, int tid) {
    u32 dst0 = sb + SM_B + buf * B_SZ;
    const char* src0 = (const char*)g_ef + chunk * (CHUNK * KTOT * 2);  // dense 16384B
    for (int i = tid; i < CHUNK * 16; i += THREADS) {   // 16 x 16B segs per 256B row
        int r = i >> 4, s = i & 15;
        CP16(dst0 + r * (KP * 2) + s * 16, src0 + i * 16);
    }
}

__global__ void __launch_bounds__(THREADS, 2) vq_argmin_mma(const float* __restrict__ z) {
    extern __shared__ char smem[];
    const u32 sb  = smem_u32(smem);
    const int tid = threadIdx.x;
    const int w   = tid >> 5, l = tid & 31;
    const int wm  = w & 1, wn = w >> 1;          // 2 x 4 warp grid
    const int blk = blockIdx.x;
    const int n0  = blk * TOK_CTA;

    float* e2s = (float*)(smem + SM_E2);
    for (int i = tid; i < K_CODES; i += THREADS) e2s[i] = g_e2[i];

    // ---- prologue: stage z [64][128] floats, split into A [128][128] halves
    {
        float* zst = (float*)(smem + SM_B);      // 64 x 132 floats (33792B <= 34816B)
        const float* zsrc = z + (n0 >> 12) * (D_DIM * 4096) + (n0 & 4095);
        for (int i = tid; i < 2048; i += THREADS) {       // 64 d x 32 float4
            int d = i >> 5, g = (i & 31) << 2;
            *(float4*)(zst + d * 132 + g) = *(const float4*)(zsrc + d * 4096 + g);
        }
        __syncthreads();
        __half* As = (__half*)(smem + SM_A);
        int r = tid >> 1, d0 = (tid & 1) << 5;
#pragma unroll
        for (int j = 0; j < 32; j++) {
            int d = d0 + j;
            float v = zst[d * 132 + r];
            __half h = __float2half_rn(v);
            __half m = __float2half_rn(v - __half2float(h));
            As[r * KP + d]      = h;   // x e_h
            As[r * KP + 64 + d] = m;   // x e_h   -> sum = z . e_h
        }
        __syncthreads();
    }

    issue_B(sb, 0, 0, tid);
    CP_COMMIT();

    // per-thread running top-2: 4 m-tiles x 2 row-halves = 8 slots
    float v1[8], v2[8];
    int   i1[8], i2[8];
#pragma unroll
    for (int q = 0; q < 8; q++) { v1[q] = v2[q] = 3.4e38f; i1[q] = i2[q] = 0; }

    // ldmatrix lane address offsets (halves): row = l&15, colgrp = (l>>4)*8
    const u32 a_lane = sb + SM_A + (u32)(((wm * 64 + (l & 15)) * KP + (l >> 4) * 8) * 2);
    const u32 b_lane_off = (u32)(((wn * 16 + (l & 15)) * KP + (l >> 4) * 8) * 2);

    for (int c = 0; c < NCHUNK; c++) {
        if (c < NCHUNK - 1) { issue_B(sb, (c + 1) & 1, c + 1, tid); CP_COMMIT(); }
        if (c < NCHUNK - 1) CP_WAIT1(); else CP_WAIT0();
        __syncthreads();

        const u32 b_base = sb + SM_B + (u32)((c & 1) * B_SZ) + b_lane_off;

        float acc[4][2][4];
#pragma unroll
        for (int mt = 0; mt < 4; mt++)
#pragma unroll
            for (int nt = 0; nt < 2; nt++)
#pragma unroll
                for (int q = 0; q < 4; q++) acc[mt][nt][q] = 0.f;

#pragma unroll
        for (int ks = 0; ks < KTOT / 16; ks++) {
            const u32 ko = ks * 32;                 // 16 halves = 32 B
            u32 af[4][4], bf[4];
#pragma unroll
            for (int mt = 0; mt < 4; mt++) LDSM4(af[mt], a_lane + mt * (16 * KP * 2) + ko);
            LDSM4(bf, b_base + ko);
#pragma unroll
            for (int mt = 0; mt < 4; mt++) {
                MMA16816(acc[mt][0], af[mt], bf[0], bf[2]);
                MMA16816(acc[mt][1], af[mt], bf[1], bf[3]);
            }
        }

        // ---- scores + running top-2 (codes ascend: strict < keeps first) ---
        const int cb = c * CHUNK + wn * 16 + (l & 3) * 2;
#pragma unroll
        for (int mt = 0; mt < 4; mt++) {
#pragma unroll
            for (int nt = 0; nt < 2; nt++) {
                int code = cb + nt * 8;
                float2 e2p = *(const float2*)(e2s + code);
                float s0 = fmaf(-2.f, acc[mt][nt][0], e2p.x);
                float s1 = fmaf(-2.f, acc[mt][nt][1], e2p.y);
                float s2 = fmaf(-2.f, acc[mt][nt][2], e2p.x);
                float s3 = fmaf(-2.f, acc[mt][nt][3], e2p.y);
                int q0 = mt * 2, q1 = mt * 2 + 1;
                if (s0 < v1[q0]) { v2[q0] = v1[q0]; i2[q0] = i1[q0]; v1[q0] = s0; i1[q0] = code; }
                else if (s0 < v2[q0]) { v2[q0] = s0; i2[q0] = code; }
                if (s1 < v1[q0]) { v2[q0] = v1[q0]; i2[q0] = i1[q0]; v1[q0] = s1; i1[q0] = code + 1; }
                else if (s1 < v2[q0]) { v2[q0] = s1; i2[q0] = code + 1; }
                if (s2 < v1[q1]) { v2[q1] = v1[q1]; i2[q1] = i1[q1]; v1[q1] = s2; i1[q1] = code; }
                else if (s2 < v2[q1]) { v2[q1] = s2; i2[q1] = code; }
                if (s3 < v1[q1]) { v2[q1] = v1[q1]; i2[q1] = i1[q1]; v1[q1] = s3; i1[q1] = code + 1; }
                else if (s3 < v2[q1]) { v2[q1] = s3; i2[q1] = code + 1; }
            }
        }
        __syncthreads();   // all reads of B buf done before it is refilled
    }

    // ---- dump all 16 slot-top-2s per token, then select approx top-8 ------
    float* sv1 = (float*)(smem + SV1_OFF);   // [128][16]
    int*   si1 = (int*)  (smem + SI1_OFF);
    float* sv2 = (float*)(smem + SV2_OFF);
    int*   si2 = (int*)  (smem + SI2_OFF);
    const int scol = wn * 4 + (l & 3);
#pragma unroll
    for (int q = 0; q < 8; q++) {
        int row = wm * 64 + (q >> 1) * 16 + (q & 1) * 8 + (l >> 2);
        sv1[row * 16 + scol] = v1[q]; si1[row * 16 + scol] = i1[q];
        sv2[row * 16 + scol] = v2[q]; si2[row * 16 + scol] = i2[q];
    }
    __syncthreads();
    if (tid < TOK_CTA) {
        u32 used = 0;
        int* cout = g_cand + (n0 + tid) * NCAND;
#pragma unroll
        for (int p = 0; p < NCAND; p++) {
            float bv = 3.4e38f; int bi = 0x7fffffff, bj = 0;
#pragma unroll
            for (int j = 0; j < 32; j++) {
                if ((used >> j) & 1u) continue;
                int slot = j >> 1;
                float v = (j & 1) ? sv2[tid * 16 + slot] : sv1[tid * 16 + slot];
                int   i = (j & 1) ? si2[tid * 16 + slot] : si1[tid * 16 + slot];
                if (v < bv || (v == bv && i < bi)) { bv = v; bi = i; bj = j; }
            }
            used |= 1u << bj;
            cout[p] = bi;
        }
    }
}

// ---------------------------------------------------------------------------
// K1b: exact fp32 refine over 8 candidates (bitwise round-2 comparator)
// ---------------------------------------------------------------------------
__global__ void vq_refine8(const float* __restrict__ z, const float* __restrict__ emb) {
    int n = blockIdx.x * blockDim.x + threadIdx.x;
    int b = n >> 12, hw = n & 4095;
    const float* zp = z + b * (D_DIM * 4096) + hw;
    int cs[NCAND];
#pragma unroll
    for (int k = 0; k < NCAND; k++) cs[k] = g_cand[n * NCAND + k];
    float dot[NCAND];
#pragma unroll
    for (int k = 0; k < NCAND; k++) dot[k] = 0.f;
#pragma unroll
    for (int d = 0; d < D_DIM; d++) {
        float zv = zp[d * 4096];
#pragma unroll
        for (int k = 0; k < NCAND; k++)
            dot[k] = fmaf(zv, emb[cs[k] * D_DIM + d], dot[k]);
    }
    float bv = 3.4e38f; int bi = 0x7fffffff;
#pragma unroll
    for (int k = 0; k < NCAND; k++) {
        float s = fmaf(-2.f, dot[k], g_e2[cs[k]]);
        if (s < bv || (s == bv && cs[k] < bi)) { bv = s; bi = cs[k]; }
    }
    g_idx[n] = bi;
}

// ---------------------------------------------------------------------------
// K2: gather zq, straight-through out [B,D,H,W], loss partials  (R10 form)
// ---------------------------------------------------------------------------
__global__ void vq_gather(const float* __restrict__ z, const float* __restrict__ emb,
                          float* __restrict__ out) {
    int i = blockIdx.x * blockDim.x + threadIdx.x;
    int o = i << 2;
    int r = o & 4095;
    int d = (o >> 12) & 63;
    int b = o >> 18;
    int n = (b << 12) + r;
    float4 zv = *(const float4*)(z + o);
    int i0 = g_idx[n], i1 = g_idx[n + 1], i2 = g_idx[n + 2], i3 = g_idx[n + 3];
    float q0 = emb[i0 * 64 + d];
    float q1 = emb[i1 * 64 + d];
    float q2 = emb[i2 * 64 + d];
    float q3 = emb[i3 * 64 + d];
    float t0 = q0 - zv.x, t1 = q1 - zv.y, t2 = q2 - zv.z, t3 = q3 - zv.w;
    float4 ov = { zv.x + t0, zv.y + t1, zv.z + t2, zv.w + t3 };
    *(float4*)(out + o) = ov;

    float ls = t0 * t0 + t1 * t1 + t2 * t2 + t3 * t3;
#pragma unroll
    for (int off = 16; off; off >>= 1) ls += __shfl_xor_sync(0xffffffffu, ls, off);
    __shared__ float wsum[8];
    int lane = threadIdx.x & 31, ww = threadIdx.x >> 5;
    if (lane == 0) wsum[ww] = ls;
    __syncthreads();
    if (threadIdx.x == 0) {
        float s = 0.f;
#pragma unroll
        for (int j = 0; j < 8; j++) s += wsum[j];
        atomicAdd(&g_loss, (double)s);
    }
}

__global__ void vq_final(float* __restrict__ out, int loc) {
    if (threadIdx.x == 0 && blockIdx.x == 0)
        out[loc] = (float)(g_loss * (1.25 / 8388608.0));
}

// ---------------------------------------------------------------------------
extern "C" void kernel_launch(void* const* d_in, const int* in_sizes, int n_in,
                              void* d_out, int out_size) {
    const float* z   = (const float*)d_in[0];
    const float* emb = (const float*)d_in[1];
    float* out = (float*)d_out;

    cudaFuncSetAttribute(vq_argmin_mma, cudaFuncAttributeMaxDynamicSharedMemorySize, SMEM_TOTAL);

    vq_prep      <<<32, 256>>>(emb);
    vq_argmin_mma<<<NCTA, THREADS, SMEM_TOTAL>>>(z);
    vq_refine8   <<<N_TOK / 256, 256>>>(z, emb);
    vq_gather    <<<(N_TOK * D_DIM) / (4 * 256), 256>>>(z, emb, out);
    vq_final     <<<1, 32>>>(out, out_size - 1);
}

// round 14
// speedup vs baseline: 1.4837x; 1.4837x over previous
#include <cuda_runtime.h>
#include <cuda_fp16.h>

// ---------------------------------------------------------------------------
// VQ-VAE vector quantizer: fp16-split HMMA GEMM ranks codes (top-2 candidates),
// then an exact-fp32 refine (bitwise round-2 scalar arithmetic) decides.
//   z: [32, 64, 64, 64] fp32, emb_w: [1024, 64] fp32.
// R14: EXACT R10 kernels (best measured: 368.7us). Two empty dummy launches
//      inserted so vq_argmin_mma is the 4th launch -> ncu finally profiles it
//      (observed: the capture always lands on the 4th kernel in program order).
// ---------------------------------------------------------------------------

#define N_TOK    131072
#define K_CODES  1024
#define D_DIM    64
#define TOK_CTA  128
#define NCTA     (N_TOK / TOK_CTA)     // 1024
#define CHUNK    64                    // codes per chunk
#define NCHUNK   (K_CODES / CHUNK)     // 16
#define KTOT     192                   // 3 x 64 split segments (hh, mh, hm)
#define KP       200                   // padded smem stride (halves); 400B rows
#define THREADS  256

#define A_SZ     (TOK_CTA * KP * 2)    // 51200 B
#define B_SZ     (CHUNK * KP * 2)      // 25600 B per buffer
#define SM_A     0
#define SM_B     A_SZ                  // two buffers
#define SM_E2    (SM_A + A_SZ + 2 * B_SZ)   // 102400
#define SMEM_TOTAL (SM_E2 + K_CODES * 4)    // 106496  -> 2 CTAs/SM

typedef unsigned int u32;

__device__ __align__(16) __half g_ef[K_CODES * KTOT];  // [code][k] k-contig
__device__ float  g_e2[K_CODES];
__device__ int    g_c1[N_TOK];         // approx argmin
__device__ int    g_c2[N_TOK];         // approx runner-up
__device__ int    g_idx[N_TOK];        // refined argmin
__device__ double g_loss;

// ---------------- PTX helpers ----------------------------------------------
__device__ __forceinline__ u32 smem_u32(const void* p) {
    u32 a;
    asm("{ .reg .u64 t; cvta.to.shared.u64 t, %1; cvt.u32.u64 %0, t; }" : "=r"(a) : "l"(p));
    return a;
}
#define LDSM4(r, addr)                                                                   \
    asm volatile("ldmatrix.sync.aligned.m8n8.x4.shared.b16 {%0,%1,%2,%3}, [%4];"         \
        : "=r"((r)[0]), "=r"((r)[1]), "=r"((r)[2]), "=r"((r)[3]) : "r"(addr))
#define MMA16816(d, a, b0, b1)                                                           \
    asm volatile("mma.sync.aligned.m16n8k16.row.col.f32.f16.f16.f32 "                    \
        "{%0,%1,%2,%3}, {%4,%5,%6,%7}, {%8,%9}, {%0,%1,%2,%3};"                          \
        : "+f"((d)[0]), "+f"((d)[1]), "+f"((d)[2]), "+f"((d)[3])                         \
        : "r"((a)[0]), "r"((a)[1]), "r"((a)[2]), "r"((a)[3]), "r"(b0), "r"(b1))
#define CP16(dst, src)                                                                   \
    asm volatile("cp.async.cg.shared.global [%0], [%1], 16;" :: "r"(dst), "l"(src))
#define CP_COMMIT() asm volatile("cp.async.commit_group;" ::: "memory")
#define CP_WAIT1()  asm volatile("cp.async.wait_group 1;" ::: "memory")
#define CP_WAIT0()  asm volatile("cp.async.wait_group 0;" ::: "memory")

// lexicographic (value, index) compare: a < b ?
__device__ __forceinline__ bool vless(float av, int ai, float bv, int bi) {
    return av < bv || (av == bv && ai < bi);
}
// merge two sorted top-2 pairs
__device__ __forceinline__ void merge2(float& v1, int& i1, float& v2, int& i2,
                                       float w1, int j1, float w2, int j2) {
    if (vless(w1, j1, v1, i1)) {
        float nv2; int ni2;
        if (vless(v1, i1, w2, j2)) { nv2 = v1; ni2 = i1; } else { nv2 = w2; ni2 = j2; }
        v1 = w1; i1 = j1; v2 = nv2; i2 = ni2;
    } else if (vless(w1, j1, v2, i2)) {
        v2 = w1; i2 = j1;
    }
}

// ---------------------------------------------------------------------------
// K0: split codebook into fp16 h/m segments, compute ||e||^2, zero loss
// ---------------------------------------------------------------------------
__global__ void vq_prep(const float* __restrict__ emb) {
    int t = blockIdx.x * blockDim.x + threadIdx.x;   // 8192 threads
    if (t == 0) g_loss = 0.0;
    for (int i = t; i < K_CODES * D_DIM; i += 8192) {
        int c = i >> 6, k = i & 63;
        float v = emb[i];
        __half h = __float2half_rn(v);
        __half m = __float2half_rn(v - __half2float(h));
        g_ef[c * KTOT + k]       = h;   // pairs with z_h  -> hh
        g_ef[c * KTOT + 64 + k]  = h;   // pairs with z_m  -> mh
        g_ef[c * KTOT + 128 + k] = m;   // pairs with z_h  -> hm
    }
    if (t < K_CODES) {
        const float4* row = (const float4*)(emb + t * D_DIM);
        float s = 0.f;
#pragma unroll
        for (int i = 0; i < 16; i++) {
            float4 v = row[i];
            s += v.x * v.x + v.y * v.y + v.z * v.z + v.w * v.w;
        }
        g_e2[t] = s;
    }
}

// dummy launches: shift vq_argmin_mma into the profiler's capture slot (#4)
__global__ void vq_dummy() {}

// ---------------------------------------------------------------------------
// K1: HMMA candidate ranking. 1024 CTAs x 128 tokens. 8 warps (2M x 4N),
// warp tile 64 x 16, chunk = 64 codes double-buffered.  (EXACT R10 form.)
// ---------------------------------------------------------------------------
__device__ __forceinline__ void issue_B(u32 sb, int buf, int chunk, int tid) {
    u32 dst0 = sb + SM_B + buf * B_SZ;
    const char* src0 = (const char*)g_ef + chunk * (CHUNK * KTOT * 2);  // dense 24576B
    for (int i = tid; i < CHUNK * 24; i += THREADS) {   // 24 x 16B segs per 384B row
        int r = i / 24, s = i - r * 24;
        CP16(dst0 + r * (KP * 2) + s * 16, src0 + i * 16);
    }
}

__global__ void __launch_bounds__(THREADS, 2) vq_argmin_mma(const float* __restrict__ z) {
    extern __shared__ char smem[];
    const u32 sb  = smem_u32(smem);
    const int tid = threadIdx.x;
    const int w   = tid >> 5, l = tid & 31;
    const int wm  = w & 1, wn = w >> 1;          // 2 x 4 warp grid
    const int blk = blockIdx.x;
    const int n0  = blk * TOK_CTA;

    float* e2s = (float*)(smem + SM_E2);
    for (int i = tid; i < K_CODES; i += THREADS) e2s[i] = g_e2[i];

    // ---- prologue: stage z [64][128] floats, split into A [128][192] halves
    {
        float* zst = (float*)(smem + SM_B);      // 64 x 132 floats, fits both B bufs
        const float* zsrc = z + (n0 >> 12) * (D_DIM * 4096) + (n0 & 4095);
        for (int i = tid; i < 2048; i += THREADS) {       // 64 d x 32 float4
            int d = i >> 5, g = (i & 31) << 2;
            *(float4*)(zst + d * 132 + g) = *(const float4*)(zsrc + d * 4096 + g);
        }
        __syncthreads();
        __half* As = (__half*)(smem + SM_A);
        int r = tid >> 1, d0 = (tid & 1) << 5;
#pragma unroll
        for (int j = 0; j < 32; j++) {
            int d = d0 + j;
            float v = zst[d * 132 + r];
            __half h = __float2half_rn(v);
            __half m = __float2half_rn(v - __half2float(h));
            As[r * KP + d]       = h;    // x e_h -> hh
            As[r * KP + 64 + d]  = m;    // x e_h -> mh
            As[r * KP + 128 + d] = h;    // x e_m -> hm
        }
        __syncthreads();
    }

    issue_B(sb, 0, 0, tid);
    CP_COMMIT();

    // per-thread running top-2: 4 m-tiles x 2 row-halves
    float v1[8], v2[8];
    int   i1[8], i2[8];
#pragma unroll
    for (int q = 0; q < 8; q++) { v1[q] = v2[q] = 3.4e38f; i1[q] = i2[q] = 0; }

    // ldmatrix lane address offsets (halves): row = l&15, colgrp = (l>>4)*8
    const u32 a_lane = sb + SM_A + (u32)(((wm * 64 + (l & 15)) * KP + (l >> 4) * 8) * 2);
    const u32 b_lane_off = (u32)(((wn * 16 + (l & 15)) * KP + (l >> 4) * 8) * 2);

    for (int c = 0; c < NCHUNK; c++) {
        if (c < NCHUNK - 1) { issue_B(sb, (c + 1) & 1, c + 1, tid); CP_COMMIT(); }
        if (c < NCHUNK - 1) CP_WAIT1(); else CP_WAIT0();
        __syncthreads();

        const u32 b_base = sb + SM_B + (u32)((c & 1) * B_SZ) + b_lane_off;

        float acc[4][2][4];
#pragma unroll
        for (int mt = 0; mt < 4; mt++)
#pragma unroll
            for (int nt = 0; nt < 2; nt++)
#pragma unroll
                for (int q = 0; q < 4; q++) acc[mt][nt][q] = 0.f;

#pragma unroll
        for (int ks = 0; ks < KTOT / 16; ks++) {
            const u32 ko = ks * 32;                 // 16 halves = 32 B
            u32 af[4][4], bf[4];
#pragma unroll
            for (int mt = 0; mt < 4; mt++) LDSM4(af[mt], a_lane + mt * (16 * KP * 2) + ko);
            LDSM4(bf, b_base + ko);
#pragma unroll
            for (int mt = 0; mt < 4; mt++) {
                MMA16816(acc[mt][0], af[mt], bf[0], bf[2]);
                MMA16816(acc[mt][1], af[mt], bf[1], bf[3]);
            }
        }

        // ---- scores + running top-2 (codes ascend: strict < keeps first) ---
        const int cb = c * CHUNK + wn * 16 + (l & 3) * 2;
#pragma unroll
        for (int mt = 0; mt < 4; mt++) {
#pragma unroll
            for (int nt = 0; nt < 2; nt++) {
                int code = cb + nt * 8;
                float2 e2p = *(const float2*)(e2s + code);
                float s0 = fmaf(-2.f, acc[mt][nt][0], e2p.x);
                float s1 = fmaf(-2.f, acc[mt][nt][1], e2p.y);
                float s2 = fmaf(-2.f, acc[mt][nt][2], e2p.x);
                float s3 = fmaf(-2.f, acc[mt][nt][3], e2p.y);
                int q0 = mt * 2, q1 = mt * 2 + 1;
                if (s0 < v1[q0]) { v2[q0] = v1[q0]; i2[q0] = i1[q0]; v1[q0] = s0; i1[q0] = code; }
                else if (s0 < v2[q0]) { v2[q0] = s0; i2[q0] = code; }
                if (s1 < v1[q0]) { v2[q0] = v1[q0]; i2[q0] = i1[q0]; v1[q0] = s1; i1[q0] = code + 1; }
                else if (s1 < v2[q0]) { v2[q0] = s1; i2[q0] = code + 1; }
                if (s2 < v1[q1]) { v2[q1] = v1[q1]; i2[q1] = i1[q1]; v1[q1] = s2; i1[q1] = code; }
                else if (s2 < v2[q1]) { v2[q1] = s2; i2[q1] = code; }
                if (s3 < v1[q1]) { v2[q1] = v1[q1]; i2[q1] = i1[q1]; v1[q1] = s3; i1[q1] = code + 1; }
                else if (s3 < v2[q1]) { v2[q1] = s3; i2[q1] = code + 1; }
            }
        }
        __syncthreads();   // all reads of B buf done before it is refilled
    }

    // ---- reduce top-2 across quad lanes (l&3), then across warp_n via smem -
#pragma unroll
    for (int q = 0; q < 8; q++) {
#pragma unroll
        for (int off = 1; off <= 2; off <<= 1) {
            float w1 = __shfl_xor_sync(0xffffffffu, v1[q], off);
            int   j1 = __shfl_xor_sync(0xffffffffu, i1[q], off);
            float w2 = __shfl_xor_sync(0xffffffffu, v2[q], off);
            int   j2 = __shfl_xor_sync(0xffffffffu, i2[q], off);
            merge2(v1[q], i1[q], v2[q], i2[q], w1, j1, w2, j2);
        }
    }
    float* sv1 = (float*)(smem + SM_B);          // [128][4]
    int*   si1 = (int*)(smem + SM_B + 2048);
    float* sv2 = (float*)(smem + SM_B + 4096);
    int*   si2 = (int*)(smem + SM_B + 6144);
    if ((l & 3) == 0) {
#pragma unroll
        for (int q = 0; q < 8; q++) {
            int row = wm * 64 + (q >> 1) * 16 + (q & 1) * 8 + (l >> 2);
            sv1[row * 4 + wn] = v1[q]; si1[row * 4 + wn] = i1[q];
            sv2[row * 4 + wn] = v2[q]; si2[row * 4 + wn] = i2[q];
        }
    }
    __syncthreads();
    if (tid < TOK_CTA) {
        float bv1 = sv1[tid * 4], bv2 = sv2[tid * 4];
        int   bi1 = si1[tid * 4], bi2 = si2[tid * 4];
#pragma unroll
        for (int t = 1; t < 4; t++)
            merge2(bv1, bi1, bv2, bi2,
                   sv1[tid * 4 + t], si1[tid * 4 + t],
                   sv2[tid * 4 + t], si2[tid * 4 + t]);
        g_c1[n0 + tid] = bi1;
        g_c2[n0 + tid] = bi2;
    }
}

// ---------------------------------------------------------------------------
// K1b: exact fp32 refine between the two candidates (bitwise R2 arithmetic)
// ---------------------------------------------------------------------------
__global__ void vq_refine(const float* __restrict__ z, const float* __restrict__ emb) {
    int n = blockIdx.x * blockDim.x + threadIdx.x;
    int b = n >> 12, hw = n & 4095;
    const float* zp = z + b * (D_DIM * 4096) + hw;
    int c1 = g_c1[n], c2 = g_c2[n];
    const float* e1 = emb + c1 * D_DIM;
    const float* e2 = emb + c2 * D_DIM;
    float d1 = 0.f, d2 = 0.f;
#pragma unroll
    for (int d = 0; d < D_DIM; d++) {
        float zv = zp[d * 4096];
        d1 = fmaf(zv, e1[d], d1);
        d2 = fmaf(zv, e2[d], d2);
    }
    float s1 = fmaf(-2.f, d1, g_e2[c1]);
    float s2 = fmaf(-2.f, d2, g_e2[c2]);
    g_idx[n] = (s2 < s1 || (s2 == s1 && c2 < c1)) ? c2 : c1;
}

// ---------------------------------------------------------------------------
// K2: gather zq, straight-through out [B,D,H,W], loss partials
// ---------------------------------------------------------------------------
__global__ void vq_gather(const float* __restrict__ z, const float* __restrict__ emb,
                          float* __restrict__ out) {
    int i = blockIdx.x * blockDim.x + threadIdx.x;
    int o = i << 2;
    int r = o & 4095;
    int d = (o >> 12) & 63;
    int b = o >> 18;
    int n = (b << 12) + r;
    float4 zv = *(const float4*)(z + o);
    int i0 = g_idx[n], i1 = g_idx[n + 1], i2 = g_idx[n + 2], i3 = g_idx[n + 3];
    float q0 = emb[i0 * 64 + d];
    float q1 = emb[i1 * 64 + d];
    float q2 = emb[i2 * 64 + d];
    float q3 = emb[i3 * 64 + d];
    float t0 = q0 - zv.x, t1 = q1 - zv.y, t2 = q2 - zv.z, t3 = q3 - zv.w;
    float4 ov = { zv.x + t0, zv.y + t1, zv.z + t2, zv.w + t3 };
    *(float4*)(out + o) = ov;

    float ls = t0 * t0 + t1 * t1 + t2 * t2 + t3 * t3;
#pragma unroll
    for (int off = 16; off; off >>= 1) ls += __shfl_xor_sync(0xffffffffu, ls, off);
    __shared__ float wsum[8];
    int lane = threadIdx.x & 31, ww = threadIdx.x >> 5;
    if (lane == 0) wsum[ww] = ls;
    __syncthreads();
    if (threadIdx.x == 0) {
        float s = 0.f;
#pragma unroll
        for (int j = 0; j < 8; j++) s += wsum[j];
        atomicAdd(&g_loss, (double)s);
    }
}

__global__ void vq_final(float* __restrict__ out, int loc) {
    if (threadIdx.x == 0 && blockIdx.x == 0)
        out[loc] = (float)(g_loss * (1.25 / 8388608.0));
}

// ---------------------------------------------------------------------------
extern "C" void kernel_launch(void* const* d_in, const int* in_sizes, int n_in,
                              void* d_out, int out_size) {
    const float* z   = (const float*)d_in[0];
    const float* emb = (const float*)d_in[1];
    float* out = (float*)d_out;

    cudaFuncSetAttribute(vq_argmin_mma, cudaFuncAttributeMaxDynamicSharedMemorySize, SMEM_TOTAL);

    vq_prep      <<<32, 256>>>(emb);
    vq_dummy     <<<1, 32>>>();          // launch #2 (profiler alignment)
    vq_dummy     <<<1, 32>>>();          // launch #3 (profiler alignment)
    vq_argmin_mma<<<NCTA, THREADS, SMEM_TOTAL>>>(z);   // launch #4 -> profiled
    vq_refine    <<<N_TOK / 256, 256>>>(z, emb);
    vq_gather    <<<(N_TOK * D_DIM) / (4 * 256), 256>>>(z, emb, out);
    vq_final     <<<1, 32>>>(out, out_size - 1);
}

// round 17
// speedup vs baseline: 1.6740x; 1.1283x over previous
#include <cuda_runtime.h>
#include <cuda_fp16.h>

// ---------------------------------------------------------------------------
// VQ-VAE vector quantizer: fp16-split HMMA GEMM ranks codes (top-2 candidates),
// then an exact-fp32 refine (bitwise round-2 scalar arithmetic) decides.
//   z: [32, 64, 64, 64] fp32, emb_w: [1024, 64] fp32.
// R15 (from R14 profile: occ 23%, issue 45%, epilogue fma/alu = 80% of issue):
//   3 CTAs/SM: CHUNK 64->32, no z-staging (direct coalesced LDG prologue),
//   e2 via __ldg (smem 106496 -> 76800), 4Mx2N warp grid (regs 100 -> ~70,
//   top-2 slots 8 -> 4), __launch_bounds__(256,3).
//   Pipeline/barriers EXACTLY R10's proven form. Numerics unchanged.
// ---------------------------------------------------------------------------

#define N_TOK    131072
#define K_CODES  1024
#define D_DIM    64
#define TOK_CTA  128
#define NCTA     (N_TOK / TOK_CTA)     // 1024
#define CHUNK    32                    // codes per chunk
#define NCHUNK   (K_CODES / CHUNK)     // 32
#define KTOT     192                   // 3 x 64 split segments (hh, mh, hm)
#define KP       200                   // padded smem stride (halves); 400B rows
#define THREADS  256

#define A_SZ     (TOK_CTA * KP * 2)    // 51200 B
#define B_SZ     (CHUNK * KP * 2)      // 12800 B per buffer
#define SM_A     0
#define SM_B     A_SZ                  // two buffers
#define SMEM_TOTAL (SM_B + 2 * B_SZ)   // 76800  -> 3 CTAs/SM (3x76800 <= 233472)

typedef unsigned int u32;

__device__ __align__(16) __half g_ef[K_CODES * KTOT];  // [code][k] k-contig
__device__ __align__(8) float g_e2[K_CODES];
__device__ int    g_c1[N_TOK];         // approx argmin
__device__ int    g_c2[N_TOK];         // approx runner-up
__device__ int    g_idx[N_TOK];        // refined argmin
__device__ double g_loss;

// ---------------- PTX helpers ----------------------------------------------
__device__ __forceinline__ u32 smem_u32(const void* p) {
    u32 a;
    asm("{ .reg .u64 t; cvta.to.shared.u64 t, %1; cvt.u32.u64 %0, t; }" : "=r"(a) : "l"(p));
    return a;
}
#define LDSM4(r, addr)                                                                   \
    asm volatile("ldmatrix.sync.aligned.m8n8.x4.shared.b16 {%0,%1,%2,%3}, [%4];"         \
        : "=r"((r)[0]), "=r"((r)[1]), "=r"((r)[2]), "=r"((r)[3]) : "r"(addr))
#define MMA16816(d, a, b0, b1)                                                           \
    asm volatile("mma.sync.aligned.m16n8k16.row.col.f32.f16.f16.f32 "                    \
        "{%0,%1,%2,%3}, {%4,%5,%6,%7}, {%8,%9}, {%0,%1,%2,%3};"                          \
        : "+f"((d)[0]), "+f"((d)[1]), "+f"((d)[2]), "+f"((d)[3])                         \
        : "r"((a)[0]), "r"((a)[1]), "r"((a)[2]), "r"((a)[3]), "r"(b0), "r"(b1))
#define CP16(dst, src)                                                                   \
    asm volatile("cp.async.cg.shared.global [%0], [%1], 16;" :: "r"(dst), "l"(src))
#define CP_COMMIT() asm volatile("cp.async.commit_group;" ::: "memory")
#define CP_WAIT1()  asm volatile("cp.async.wait_group 1;" ::: "memory")
#define CP_WAIT0()  asm volatile("cp.async.wait_group 0;" ::: "memory")

// lexicographic (value, index) compare: a < b ?
__device__ __forceinline__ bool vless(float av, int ai, float bv, int bi) {
    return av < bv || (av == bv && ai < bi);
}
// merge two sorted top-2 pairs
__device__ __forceinline__ void merge2(float& v1, int& i1, float& v2, int& i2,
                                       float w1, int j1, float w2, int j2) {
    if (vless(w1, j1, v1, i1)) {
        float nv2; int ni2;
        if (vless(v1, i1, w2, j2)) { nv2 = v1; ni2 = i1; } else { nv2 = w2; ni2 = j2; }
        v1 = w1; i1 = j1; v2 = nv2; i2 = ni2;
    } else if (vless(w1, j1, v2, i2)) {
        v2 = w1; i2 = j1;
    }
}

// ---------------------------------------------------------------------------
// K0: split codebook into fp16 h/m segments, compute ||e||^2, zero loss
// ---------------------------------------------------------------------------
__global__ void vq_prep(const float* __restrict__ emb) {
    int t = blockIdx.x * blockDim.x + threadIdx.x;   // 8192 threads
    if (t == 0) g_loss = 0.0;
    for (int i = t; i < K_CODES * D_DIM; i += 8192) {
        int c = i >> 6, k = i & 63;
        float v = emb[i];
        __half h = __float2half_rn(v);
        __half m = __float2half_rn(v - __half2float(h));
        g_ef[c * KTOT + k]       = h;   // pairs with z_h  -> hh
        g_ef[c * KTOT + 64 + k]  = h;   // pairs with z_m  -> mh
        g_ef[c * KTOT + 128 + k] = m;   // pairs with z_h  -> hm
    }
    if (t < K_CODES) {
        const float4* row = (const float4*)(emb + t * D_DIM);
        float s = 0.f;
#pragma unroll
        for (int i = 0; i < 16; i++) {
            float4 v = row[i];
            s += v.x * v.x + v.y * v.y + v.z * v.z + v.w * v.w;
        }
        g_e2[t] = s;
    }
}

// dummy launches: keep vq_argmin_mma in the profiler's capture slot (#4)
__global__ void vq_dummy() {}

// ---------------------------------------------------------------------------
// K1: HMMA candidate ranking. 1024 CTAs x 128 tokens. 8 warps (4M x 2N),
// warp tile 32 rows x 16 codes, chunk = 32 codes double-buffered.
// ---------------------------------------------------------------------------
__device__ __forceinline__ void issue_B(u32 sb, int buf, int chunk, int tid) {
    u32 dst0 = sb + SM_B + buf * B_SZ;
    const char* src0 = (const char*)g_ef + chunk * (CHUNK * KTOT * 2);  // dense 12288B
    for (int i = tid; i < CHUNK * 24; i += THREADS) {   // 24 x 16B segs per 384B row
        int r = i / 24, s = i - r * 24;
        CP16(dst0 + r * (KP * 2) + s * 16, src0 + i * 16);
    }
}

__global__ void __launch_bounds__(THREADS, 3) vq_argmin_mma(const float* __restrict__ z) {
    extern __shared__ char smem[];
    const u32 sb  = smem_u32(smem);
    const int tid = threadIdx.x;
    const int w   = tid >> 5, l = tid & 31;
    const int wm  = w & 3, wn = w >> 2;          // 4 M x 2 N warp grid
    const int blk = blockIdx.x;
    const int n0  = blk * TOK_CTA;

    // ---- prologue: direct coalesced z read, split into A [128][192] halves
    {
        const float* zsrc = z + (n0 >> 12) * (D_DIM * 4096) + (n0 & 4095);
        __half* As = (__half*)(smem + SM_A);
        int r = tid >> 1, d0 = (tid & 1) << 5;
#pragma unroll
        for (int j = 0; j < 32; j++) {
            int d = d0 + j;
            float v = zsrc[d * 4096 + r];    // lanes of same (tid&1): consecutive r
            __half h = __float2half_rn(v);
            __half m = __float2half_rn(v - __half2float(h));
            As[r * KP + d]       = h;    // x e_h -> hh
            As[r * KP + 64 + d]  = m;    // x e_h -> mh
            As[r * KP + 128 + d] = h;    // x e_m -> hm
        }
        __syncthreads();
    }

    issue_B(sb, 0, 0, tid);
    CP_COMMIT();

    // per-thread running top-2: 2 m-tiles x 2 row-halves = 4 slots
    float v1[4], v2[4];
    int   i1[4], i2[4];
#pragma unroll
    for (int q = 0; q < 4; q++) { v1[q] = v2[q] = 3.4e38f; i1[q] = i2[q] = 0; }

    // ldmatrix lane address offsets (halves): row = l&15, colgrp = (l>>4)*8
    const u32 a_lane = sb + SM_A + (u32)(((wm * 32 + (l & 15)) * KP + (l >> 4) * 8) * 2);
    const u32 b_lane_off = (u32)(((wn * 16 + (l & 15)) * KP + (l >> 4) * 8) * 2);

    for (int c = 0; c < NCHUNK; c++) {
        if (c < NCHUNK - 1) { issue_B(sb, (c + 1) & 1, c + 1, tid); CP_COMMIT(); }
        if (c < NCHUNK - 1) CP_WAIT1(); else CP_WAIT0();
        __syncthreads();

        const u32 b_base = sb + SM_B + (u32)((c & 1) * B_SZ) + b_lane_off;

        float acc[2][2][4];   // mt x n8 x frag
#pragma unroll
        for (int mt = 0; mt < 2; mt++)
#pragma unroll
            for (int n8 = 0; n8 < 2; n8++)
#pragma unroll
                for (int q = 0; q < 4; q++) acc[mt][n8][q] = 0.f;

#pragma unroll
        for (int ks = 0; ks < KTOT / 16; ks++) {
            const u32 ko = ks * 32;                 // 16 halves = 32 B
            u32 af[2][4], bf[4];
#pragma unroll
            for (int mt = 0; mt < 2; mt++) LDSM4(af[mt], a_lane + mt * (16 * KP * 2) + ko);
            LDSM4(bf, b_base + ko);
#pragma unroll
            for (int mt = 0; mt < 2; mt++) {
                MMA16816(acc[mt][0], af[mt], bf[0], bf[2]);
                MMA16816(acc[mt][1], af[mt], bf[1], bf[3]);
            }
        }

        // ---- scores + running top-2 (codes ascend: strict < keeps first) ---
        const int cb = c * CHUNK + wn * 16 + (l & 3) * 2;
#pragma unroll
        for (int mt = 0; mt < 2; mt++) {
#pragma unroll
            for (int n8 = 0; n8 < 2; n8++) {
                int code = cb + n8 * 8;
                float2 e2p = __ldg((const float2*)(g_e2 + code));
                float s0 = fmaf(-2.f, acc[mt][n8][0], e2p.x);
                float s1 = fmaf(-2.f, acc[mt][n8][1], e2p.y);
                float s2 = fmaf(-2.f, acc[mt][n8][2], e2p.x);
                float s3 = fmaf(-2.f, acc[mt][n8][3], e2p.y);
                int q0 = mt * 2, q1 = mt * 2 + 1;
                if (s0 < v1[q0]) { v2[q0] = v1[q0]; i2[q0] = i1[q0]; v1[q0] = s0; i1[q0] = code; }
                else if (s0 < v2[q0]) { v2[q0] = s0; i2[q0] = code; }
                if (s1 < v1[q0]) { v2[q0] = v1[q0]; i2[q0] = i1[q0]; v1[q0] = s1; i1[q0] = code + 1; }
                else if (s1 < v2[q0]) { v2[q0] = s1; i2[q0] = code + 1; }
                if (s2 < v1[q1]) { v2[q1] = v1[q1]; i2[q1] = i1[q1]; v1[q1] = s2; i1[q1] = code; }
                else if (s2 < v2[q1]) { v2[q1] = s2; i2[q1] = code; }
                if (s3 < v1[q1]) { v2[q1] = v1[q1]; i2[q1] = i1[q1]; v1[q1] = s3; i1[q1] = code + 1; }
                else if (s3 < v2[q1]) { v2[q1] = s3; i2[q1] = code + 1; }
            }
        }
        __syncthreads();   // all reads of B buf done before it is refilled
    }

    // ---- reduce top-2 across quad lanes (l&3), then across 2 N-warps -------
#pragma unroll
    for (int q = 0; q < 4; q++) {
#pragma unroll
        for (int off = 1; off <= 2; off <<= 1) {
            float w1 = __shfl_xor_sync(0xffffffffu, v1[q], off);
            int   j1 = __shfl_xor_sync(0xffffffffu, i1[q], off);
            float w2 = __shfl_xor_sync(0xffffffffu, v2[q], off);
            int   j2 = __shfl_xor_sync(0xffffffffu, i2[q], off);
            merge2(v1[q], i1[q], v2[q], i2[q], w1, j1, w2, j2);
        }
    }
    // last chunk (c=31) used buf 1 (SM_B + B_SZ); dump region SM_B..+4KB is disjoint
    float* sv1 = (float*)(smem + SM_B);          // [128][2]
    int*   si1 = (int*)(smem + SM_B + 1024);
    float* sv2 = (float*)(smem + SM_B + 2048);
    int*   si2 = (int*)(smem + SM_B + 3072);
    if ((l & 3) == 0) {
#pragma unroll
        for (int q = 0; q < 4; q++) {
            int row = wm * 32 + (q >> 1) * 16 + (q & 1) * 8 + (l >> 2);
            sv1[row * 2 + wn] = v1[q]; si1[row * 2 + wn] = i1[q];
            sv2[row * 2 + wn] = v2[q]; si2[row * 2 + wn] = i2[q];
        }
    }
    __syncthreads();
    if (tid < TOK_CTA) {
        float bv1 = sv1[tid * 2], bv2 = sv2[tid * 2];
        int   bi1 = si1[tid * 2], bi2 = si2[tid * 2];
        merge2(bv1, bi1, bv2, bi2,
               sv1[tid * 2 + 1], si1[tid * 2 + 1],
               sv2[tid * 2 + 1], si2[tid * 2 + 1]);
        g_c1[n0 + tid] = bi1;
        g_c2[n0 + tid] = bi2;
    }
}

// ---------------------------------------------------------------------------
// K1b: exact fp32 refine between the two candidates (bitwise R2 arithmetic)
// ---------------------------------------------------------------------------
__global__ void vq_refine(const float* __restrict__ z, const float* __restrict__ emb) {
    int n = blockIdx.x * blockDim.x + threadIdx.x;
    int b = n >> 12, hw = n & 4095;
    const float* zp = z + b * (D_DIM * 4096) + hw;
    int c1 = g_c1[n], c2 = g_c2[n];
    const float* e1 = emb + c1 * D_DIM;
    const float* e2 = emb + c2 * D_DIM;
    float d1 = 0.f, d2 = 0.f;
#pragma unroll
    for (int d = 0; d < D_DIM; d++) {
        float zv = zp[d * 4096];
        d1 = fmaf(zv, e1[d], d1);
        d2 = fmaf(zv, e2[d], d2);
    }
    float s1 = fmaf(-2.f, d1, g_e2[c1]);
    float s2 = fmaf(-2.f, d2, g_e2[c2]);
    g_idx[n] = (s2 < s1 || (s2 == s1 && c2 < c1)) ? c2 : c1;
}

// ---------------------------------------------------------------------------
// K2: gather zq, straight-through out [B,D,H,W], loss partials
// ---------------------------------------------------------------------------
__global__ void vq_gather(const float* __restrict__ z, const float* __restrict__ emb,
                          float* __restrict__ out) {
    int i = blockIdx.x * blockDim.x + threadIdx.x;
    int o = i << 2;
    int r = o & 4095;
    int d = (o >> 12) & 63;
    int b = o >> 18;
    int n = (b << 12) + r;
    float4 zv = *(const float4*)(z + o);
    int i0 = g_idx[n], i1 = g_idx[n + 1], i2 = g_idx[n + 2], i3 = g_idx[n + 3];
    float q0 = emb[i0 * 64 + d];
    float q1 = emb[i1 * 64 + d];
    float q2 = emb[i2 * 64 + d];
    float q3 = emb[i3 * 64 + d];
    float t0 = q0 - zv.x, t1 = q1 - zv.y, t2 = q2 - zv.z, t3 = q3 - zv.w;
    float4 ov = { zv.x + t0, zv.y + t1, zv.z + t2, zv.w + t3 };
    *(float4*)(out + o) = ov;

    float ls = t0 * t0 + t1 * t1 + t2 * t2 + t3 * t3;
#pragma unroll
    for (int off = 16; off; off >>= 1) ls += __shfl_xor_sync(0xffffffffu, ls, off);
    __shared__ float wsum[8];
    int lane = threadIdx.x & 31, ww = threadIdx.x >> 5;
    if (lane == 0) wsum[ww] = ls;
    __syncthreads();
    if (threadIdx.x == 0) {
        float s = 0.f;
#pragma unroll
        for (int j = 0; j < 8; j++) s += wsum[j];
        atomicAdd(&g_loss, (double)s);
    }
}

__global__ void vq_final(float* __restrict__ out, int loc) {
    if (threadIdx.x == 0 && blockIdx.x == 0)
        out[loc] = (float)(g_loss * (1.25 / 8388608.0));
}

// ---------------------------------------------------------------------------
extern "C" void kernel_launch(void* const* d_in, const int* in_sizes, int n_in,
                              void* d_out, int out_size) {
    const float* z   = (const float*)d_in[0];
    const float* emb = (const float*)d_in[1];
    float* out = (float*)d_out;

    cudaFuncSetAttribute(vq_argmin_mma, cudaFuncAttributeMaxDynamicSharedMemorySize, SMEM_TOTAL);

    vq_prep      <<<32, 256>>>(emb);
    vq_dummy     <<<1, 32>>>();          // launch #2 (profiler alignment)
    vq_dummy     <<<1, 32>>>();          // launch #3 (profiler alignment)
    vq_argmin_mma<<<NCTA, THREADS, SMEM_TOTAL>>>(z);   // launch #4 -> profiled
    vq_refine    <<<N_TOK / 256, 256>>>(z, emb);
    vq_gather    <<<(N_TOK * D_DIM) / (4 * 256), 256>>>(z, emb, out);
    vq_final     <<<1, 32>>>(out, out_size - 1);
}